// round 13
// baseline (speedup 1.0000x reference)
#include <cuda_runtime.h>
#include <cuda_fp16.h>
#include <math_constants.h>

#define NODES 65536
#define DIN 64
#define DOUT 64
#define EMAX 1310720
#define CAP 96                 // slot capacity per node (Poisson(20) tail @96 ~ 1e-20)
#define GEMM_BLOCKS 1024       // NODES/64
#define SCAT_BLOCKS 512
#define OVF_CAP 1024

// Scratch (device globals — zero-initialized at module load; each run restores
// the zero invariant so graph replays are deterministic)
__device__ float   g_A[NODES * DOUT];       // X @ theta_w           (fp32, 16.8MB)
__device__ __half2 g_Bm[NODES * 32];        // X @ (phi - theta)     (fp16, 8.4MB)
__device__ int     g_cnt[NODES];            // starts 0; reduce resets to 0
__device__ int     g_slots[NODES * CAP];    // 25.2MB
__device__ int     g_ovf[2 * OVF_CAP];      // overflow (dst, src) pairs
__device__ int     g_novf;                  // starts 0; reduce resets
__device__ int     g_done;                  // completion counter; reduce resets

// Packed fp32x2 FMA (Blackwell FFMA2 — only reachable via PTX)
#define FMA_F32X2(d, a, b, c) \
    asm("fma.rn.f32x2 %0, %1, %2, %3;" : "=l"(d) : "l"(a), "l"(b), "l"(c))

// ---------------------------------------------------------------------------
// Fused GEMM + slot-scatter. Block roles interleaved 2:1 (gemm:scatter).
// GEMM: Y[N,128] = X[N,64] @ [theta | phi-theta]; cols 0..63 -> g_A (fp32),
// 64..127 -> g_Bm (fp16). Weight fusion computed in-smem from tw/pw directly.
__global__ __launch_bounds__(256) void k_gemm_scat(const float* __restrict__ X,
                                                   const int* __restrict__ src,
                                                   const int* __restrict__ dst,
                                                   const float* __restrict__ tw,
                                                   const float* __restrict__ pw,
                                                   int Nn, int E) {
    __shared__ float sX[64 * 64];    // 16 KB
    __shared__ float sW[64 * 128];   // 32 KB

    int q = blockIdx.x / 3;
    int r = blockIdx.x - q * 3;

    if (r == 2) {
        // ---- scatter role (SCAT_BLOCKS blocks, grid-stride, int4) ----
        int E4 = E >> 2;
        const int4* d4 = (const int4*)dst;
        const int4* s4 = (const int4*)src;
        for (int i = q * 256 + threadIdx.x; i < E4; i += SCAT_BLOCKS * 256) {
            int4 d = d4[i];
            int4 s = s4[i];
            int p;
            p = atomicAdd(&g_cnt[d.x], 1);
            if (p < CAP) g_slots[d.x * CAP + p] = s.x;
            else { int o = atomicAdd(&g_novf, 1); if (o < OVF_CAP) { g_ovf[2*o] = d.x; g_ovf[2*o+1] = s.x; } }
            p = atomicAdd(&g_cnt[d.y], 1);
            if (p < CAP) g_slots[d.y * CAP + p] = s.y;
            else { int o = atomicAdd(&g_novf, 1); if (o < OVF_CAP) { g_ovf[2*o] = d.y; g_ovf[2*o+1] = s.y; } }
            p = atomicAdd(&g_cnt[d.z], 1);
            if (p < CAP) g_slots[d.z * CAP + p] = s.z;
            else { int o = atomicAdd(&g_novf, 1); if (o < OVF_CAP) { g_ovf[2*o] = d.z; g_ovf[2*o+1] = s.z; } }
            p = atomicAdd(&g_cnt[d.w], 1);
            if (p < CAP) g_slots[d.w * CAP + p] = s.w;
            else { int o = atomicAdd(&g_novf, 1); if (o < OVF_CAP) { g_ovf[2*o] = d.w; g_ovf[2*o+1] = s.w; } }
        }
        int base = E4 << 2;
        if (q == 0 && threadIdx.x < (E - base)) {
            int e = base + threadIdx.x;
            int d = dst[e], s = src[e];
            int p = atomicAdd(&g_cnt[d], 1);
            if (p < CAP) g_slots[d * CAP + p] = s;
            else { int o = atomicAdd(&g_novf, 1); if (o < OVF_CAP) { g_ovf[2*o] = d; g_ovf[2*o+1] = s; } }
        }
        return;
    }

    // ---- gemm role ----
    int g = q * 2 + r;               // 0..GEMM_BLOCKS-1
    int tid = threadIdx.x;
    int blockRow = g * 64;

    const float4* xg = (const float4*)(X + (size_t)blockRow * 64);
    float4* sx4 = (float4*)sX;
#pragma unroll
    for (int i = 0; i < 4; i++) sx4[tid + i * 256] = xg[tid + i * 256];

    // Build fused weights in smem: sW[k*128 + j] = tw[k,j]; [.. +64+j] = pw - tw
    const float4* tw4 = (const float4*)tw;
    const float4* pw4 = (const float4*)pw;
#pragma unroll
    for (int i = 0; i < 4; i++) {
        int idx = tid + i * 256;             // 0..1023, covers 4096 floats
        int k = idx >> 4;
        int j4 = (idx & 15) * 4;
        float4 t = tw4[idx];
        float4 p = pw4[idx];
        *(float4*)&sW[k * 128 + j4] = t;
        *(float4*)&sW[k * 128 + 64 + j4] =
            make_float4(p.x - t.x, p.y - t.y, p.z - t.z, p.w - t.w);
    }
    __syncthreads();

    int rg = tid >> 4;     // 0..15 -> 4 rows
    int cg = tid & 15;     // 0..15 -> 8 cols
    int r0 = rg * 4;
    int c0 = cg * 8;

    // Packed accumulators: acc2[ri][jp] holds columns (c0+2*jp, c0+2*jp+1)
    unsigned long long acc2[4][4];
#pragma unroll
    for (int a = 0; a < 4; a++)
#pragma unroll
        for (int b2 = 0; b2 < 4; b2++) acc2[a][b2] = 0ull;

#pragma unroll 4
    for (int k = 0; k < 64; k++) {
        // w pairs: adjacent floats in smem ARE packed f32x2 operands
        ulonglong2 wA = *(const ulonglong2*)&sW[k * 128 + c0];      // (w0,w1),(w2,w3)
        ulonglong2 wB = *(const ulonglong2*)&sW[k * 128 + c0 + 4];  // (w4,w5),(w6,w7)
#pragma unroll
        for (int ri = 0; ri < 4; ri++) {
            float xv = sX[(r0 + ri) * 64 + k];
            unsigned int xu = __float_as_uint(xv);
            unsigned long long xx;
            asm("mov.b64 %0, {%1, %1};" : "=l"(xx) : "r"(xu));
            FMA_F32X2(acc2[ri][0], xx, wA.x, acc2[ri][0]);
            FMA_F32X2(acc2[ri][1], xx, wA.y, acc2[ri][1]);
            FMA_F32X2(acc2[ri][2], xx, wB.x, acc2[ri][2]);
            FMA_F32X2(acc2[ri][3], xx, wB.y, acc2[ri][3]);
        }
    }

#pragma unroll
    for (int ri = 0; ri < 4; ri++) {
        int row = blockRow + r0 + ri;
        if (row >= Nn) break;
        float2 a0 = *(float2*)&acc2[ri][0];
        float2 a1 = *(float2*)&acc2[ri][1];
        float2 a2 = *(float2*)&acc2[ri][2];
        float2 a3 = *(float2*)&acc2[ri][3];
        if (c0 < 64) {
            float* base = g_A + (size_t)row * 64 + c0;
            ((float4*)base)[0] = make_float4(a0.x, a0.y, a1.x, a1.y);
            ((float4*)base)[1] = make_float4(a2.x, a2.y, a3.x, a3.y);
        } else {
            __half2 hp[4];
            hp[0] = __floats2half2_rn(a0.x, a0.y);
            hp[1] = __floats2half2_rn(a1.x, a1.y);
            hp[2] = __floats2half2_rn(a2.x, a2.y);
            hp[3] = __floats2half2_rn(a3.x, a3.y);
            *(uint4*)&g_Bm[(size_t)row * 32 + ((c0 - 64) >> 1)] = *(uint4*)hp;
        }
    }
}

// ---------------------------------------------------------------------------
// Reduce: one warp per node; lane handles 2 dims (half2). Also: folds overflow
// entries (normally none), computes bias inline, resets g_cnt/g_novf/g_done
// so the next graph replay starts from the zero invariant.
__global__ __launch_bounds__(256) void k_reduce(float* __restrict__ out,
                                                const float* __restrict__ tb,
                                                const float* __restrict__ pb,
                                                int Nn) {
    int node = blockIdx.x * 8 + (threadIdx.x >> 5);
    int lane = threadIdx.x & 31;

    if (node < Nn) {
        int cnt = g_cnt[node];
        int n = min(cnt, CAP);
        const int* __restrict__ slots = g_slots + (size_t)node * CAP;

        __half nh = __ushort_as_half((unsigned short)0xFC00);   // -inf
        __half2 m = __halves2half2(nh, nh);

        int i = 0;
        for (; i + 4 <= n; i += 4) {
            int4 s = *(const int4*)&slots[i];
            __half2 v0 = g_Bm[(size_t)s.x * 32 + lane];
            __half2 v1 = g_Bm[(size_t)s.y * 32 + lane];
            __half2 v2 = g_Bm[(size_t)s.z * 32 + lane];
            __half2 v3 = g_Bm[(size_t)s.w * 32 + lane];
            m = __hmax2(m, __hmax2(__hmax2(v0, v1), __hmax2(v2, v3)));
        }
        for (; i < n; i++) {
            m = __hmax2(m, g_Bm[(size_t)slots[i] * 32 + lane]);
        }

        // Overflow fold (g_novf is 0 in practice; one broadcast load)
        int novf = g_novf;
        if (novf > 0) {
            int ne = min(novf, OVF_CAP);
            for (int e = 0; e < ne; e++) {
                if (g_ovf[2 * e] == node) {
                    m = __hmax2(m, g_Bm[(size_t)g_ovf[2 * e + 1] * 32 + lane]);
                }
            }
        }

        float2 a  = ((const float2*)g_A)[(size_t)node * 32 + lane];
        float2 bi;
        bi.x = tb[2 * lane]     + pb[2 * lane];
        bi.y = tb[2 * lane + 1] + pb[2 * lane + 1];
        float2 mf = __half22float2(m);
        float2 res;
        if (cnt > 0) {
            res.x = a.x + bi.x + mf.x;
            res.y = a.y + bi.y + mf.y;
        } else {
            res.x = 0.0f;
            res.y = 0.0f;
        }
        ((float2*)out)[(size_t)node * 32 + lane] = res;

        if (lane == 0) g_cnt[node] = 0;      // restore zero invariant
    }

    // Last-finishing block resets overflow state (all blocks have read g_novf)
    __syncthreads();
    if (threadIdx.x == 0) {
        int d = atomicAdd(&g_done, 1);
        if (d == gridDim.x - 1) {
            g_novf = 0;
            g_done = 0;
            __threadfence();
        }
    }
}

// ---------------------------------------------------------------------------
extern "C" void kernel_launch(void* const* d_in, const int* in_sizes, int n_in,
                              void* d_out, int out_size) {
    const float* h   = (const float*)d_in[0];
    const int*   src = (const int*)  d_in[1];
    const int*   dst = (const int*)  d_in[2];
    const float* tw  = (const float*)d_in[3];
    const float* tb  = (const float*)d_in[4];
    const float* pw  = (const float*)d_in[5];
    const float* pb  = (const float*)d_in[6];
    float* out = (float*)d_out;

    int Nn = in_sizes[0] / DIN;     // 65536
    int E  = in_sizes[1];           // 1310720

    k_gemm_scat<<<GEMM_BLOCKS + SCAT_BLOCKS, 256>>>(h, src, dst, tw, pw, Nn, E);
    k_reduce<<<(Nn + 7) / 8, 256>>>(out, tb, pb, Nn);
}